// round 2
// baseline (speedup 1.0000x reference)
#include <cuda_runtime.h>
#include <cuda_bf16.h>

// Problem constants
#define BB 2
#define SS 2048
#define DD 1024
#define HH 16
#define HD 64
#define MM (BB * SS)   // 4096

// Device-global scratch (allocation-free rule: __device__ arrays)
__device__ float g_q[BB * HH * SS * HD];   // [B,H,S,HD]
__device__ float g_k[BB * HH * SS * HD];
__device__ float g_v[BB * HH * SS * HD];
__device__ float g_ao[BB * SS * DD];       // [B,S,D] (heads concatenated)

// ---------------------------------------------------------------------------
// GEMM: out = X[M,K] @ W[N,K]^T + bias[N]
// BM=128, BN=128, BK=8, 256 threads, 8x8 micro-tile.
// dst_sel: 0->g_q, 1->g_k, 2->g_v (scatter to [B,H,S,HD]), 3->out_p row-major
// src_sel: 0->Xp param, 1->g_ao
// ---------------------------------------------------------------------------
__global__ __launch_bounds__(256) void gemm_bias_kernel(
    const float* __restrict__ Xp, const float* __restrict__ Wt,
    const float* __restrict__ bias, float* __restrict__ out_p,
    int src_sel, int dst_sel)
{
    const int K = 1024, N = 1024;
    const float* X = src_sel ? g_ao : Xp;
    float* out = (dst_sel == 0) ? g_q : (dst_sel == 1) ? g_k
               : (dst_sel == 2) ? g_v : out_p;

    __shared__ float As[8][128];
    __shared__ float Bs[8][128];

    int t = threadIdx.x;
    int m0 = blockIdx.y * 128;
    int n0 = blockIdx.x * 128;
    int tx = t & 15;
    int ty = t >> 4;

    float acc[8][8];
#pragma unroll
    for (int i = 0; i < 8; i++)
#pragma unroll
        for (int j = 0; j < 8; j++) acc[i][j] = 0.0f;

    int lr = t >> 1;            // 0..127
    int lseg = (t & 1) * 4;     // 0 or 4
    const float* Xbase = X + (size_t)(m0 + lr) * K + lseg;
    const float* Wbase = Wt + (size_t)(n0 + lr) * K + lseg;

    for (int k0 = 0; k0 < K; k0 += 8) {
        float4 av = *(const float4*)(Xbase + k0);
        float4 bv = *(const float4*)(Wbase + k0);
        As[lseg + 0][lr] = av.x; As[lseg + 1][lr] = av.y;
        As[lseg + 2][lr] = av.z; As[lseg + 3][lr] = av.w;
        Bs[lseg + 0][lr] = bv.x; Bs[lseg + 1][lr] = bv.y;
        Bs[lseg + 2][lr] = bv.z; Bs[lseg + 3][lr] = bv.w;
        __syncthreads();
#pragma unroll
        for (int kk = 0; kk < 8; kk++) {
            float a[8], b[8];
            *(float4*)(a)     = *(const float4*)&As[kk][ty * 8];
            *(float4*)(a + 4) = *(const float4*)&As[kk][ty * 8 + 4];
            *(float4*)(b)     = *(const float4*)&Bs[kk][tx * 8];
            *(float4*)(b + 4) = *(const float4*)&Bs[kk][tx * 8 + 4];
#pragma unroll
            for (int i = 0; i < 8; i++)
#pragma unroll
                for (int j = 0; j < 8; j++)
                    acc[i][j] += a[i] * b[j];
        }
        __syncthreads();
    }

    // epilogue
    if (dst_sel == 3) {
#pragma unroll
        for (int i = 0; i < 8; i++) {
            int m = m0 + ty * 8 + i;
#pragma unroll
            for (int j = 0; j < 8; j++) {
                int n = n0 + tx * 8 + j;
                out[(size_t)m * N + n] = acc[i][j] + bias[n];
            }
        }
    } else {
        // scatter to [B,H,S,HD]: m = b*S+s, n = h*HD+e
#pragma unroll
        for (int i = 0; i < 8; i++) {
            int m = m0 + ty * 8 + i;
            int b_ = m >> 11;       // /2048
            int s = m & 2047;
#pragma unroll
            for (int j = 0; j < 8; j++) {
                int n = n0 + tx * 8 + j;
                int h = n >> 6;
                int e = n & 63;
                out[(((size_t)(b_ * HH + h)) * SS + s) * HD + e] =
                    acc[i][j] + bias[n];
            }
        }
    }
}

// ---------------------------------------------------------------------------
// Flash attention (fp32): per CTA one (b,h) pair + one 64-row Q tile.
// 128 threads; micro-tile 8 rows x 4 cols. Online softmax with exp2f.
// Smem: Qt (Q transposed, pre-scaled), KP (K transposed, reused as P^T), Vs.
// ---------------------------------------------------------------------------
__global__ __launch_bounds__(128) void flash_attn_kernel()
{
    __shared__ float Qt[64][64];   // Qt[e][r] = Q[r][e] * 0.125 * log2(e)
    __shared__ float KP[64][64];   // Kt[e][c], then Pt[c][r]
    __shared__ float Vs[64][64];   // Vs[c][e]

    int t = threadIdx.x;
    int bh = blockIdx.y;           // 0..31
    int qt = blockIdx.x;           // 0..31
    int b_ = bh >> 4;
    int h = bh & 15;
    const float* qb = g_q + (size_t)bh * SS * HD;
    const float* kb = g_k + (size_t)bh * SS * HD;
    const float* vb = g_v + (size_t)bh * SS * HD;

    int tx = t & 15;               // 0..15 -> 4 cols
    int ty = t >> 4;               // 0..7  -> 8 rows

    const float qscale = 0.125f * 1.44269504088896340736f; // 1/sqrt(64) * log2(e)
    int q0 = qt * 64;

    // Load Q tile transposed + scaled
#pragma unroll
    for (int it = 0; it < 8; it++) {
        int idx = t + it * 128;    // 0..1023
        int r = idx >> 4;
        int sg = (idx & 15) * 4;
        float4 v4 = *(const float4*)(qb + (size_t)(q0 + r) * HD + sg);
        Qt[sg + 0][r] = v4.x * qscale;
        Qt[sg + 1][r] = v4.y * qscale;
        Qt[sg + 2][r] = v4.z * qscale;
        Qt[sg + 3][r] = v4.w * qscale;
    }

    float m_i[8], l_i[8], O[8][4];
#pragma unroll
    for (int i = 0; i < 8; i++) {
        m_i[i] = -1e30f;
        l_i[i] = 0.0f;
#pragma unroll
        for (int j = 0; j < 4; j++) O[i][j] = 0.0f;
    }

    for (int kv0 = 0; kv0 < SS; kv0 += 64) {
        // Load K tile (transposed) and V tile
#pragma unroll
        for (int it = 0; it < 8; it++) {
            int idx = t + it * 128;
            int c = idx >> 4;
            int sg = (idx & 15) * 4;
            float4 k4 = *(const float4*)(kb + (size_t)(kv0 + c) * HD + sg);
            KP[sg + 0][c] = k4.x;
            KP[sg + 1][c] = k4.y;
            KP[sg + 2][c] = k4.z;
            KP[sg + 3][c] = k4.w;
            float4 v4 = *(const float4*)(vb + (size_t)(kv0 + c) * HD + sg);
            *(float4*)&Vs[c][sg] = v4;
        }
        __syncthreads();

        // S = Q K^T (scaled, in log2 units)
        float Sreg[8][4];
#pragma unroll
        for (int i = 0; i < 8; i++)
#pragma unroll
            for (int j = 0; j < 4; j++) Sreg[i][j] = 0.0f;
#pragma unroll
        for (int e = 0; e < 64; e++) {
            float a[8], bb[4];
            *(float4*)(a)     = *(const float4*)&Qt[e][ty * 8];
            *(float4*)(a + 4) = *(const float4*)&Qt[e][ty * 8 + 4];
            *(float4*)(bb)    = *(const float4*)&KP[e][tx * 4];
#pragma unroll
            for (int i = 0; i < 8; i++)
#pragma unroll
                for (int j = 0; j < 4; j++)
                    Sreg[i][j] += a[i] * bb[j];
        }
        __syncthreads();   // before overwriting KP with P^T

        // Online softmax update + write P^T into KP
#pragma unroll
        for (int i = 0; i < 8; i++) {
            float mt = fmaxf(fmaxf(Sreg[i][0], Sreg[i][1]),
                             fmaxf(Sreg[i][2], Sreg[i][3]));
#pragma unroll
            for (int off = 8; off >= 1; off >>= 1)
                mt = fmaxf(mt, __shfl_xor_sync(0xffffffffu, mt, off));
            float mnew = fmaxf(m_i[i], mt);
            float alpha = exp2f(m_i[i] - mnew);
            m_i[i] = mnew;
            float p[4], rs = 0.0f;
#pragma unroll
            for (int j = 0; j < 4; j++) {
                p[j] = exp2f(Sreg[i][j] - mnew);
                rs += p[j];
            }
#pragma unroll
            for (int off = 8; off >= 1; off >>= 1)
                rs += __shfl_xor_sync(0xffffffffu, rs, off);
            l_i[i] = l_i[i] * alpha + rs;
#pragma unroll
            for (int j = 0; j < 4; j++) O[i][j] *= alpha;
#pragma unroll
            for (int j = 0; j < 4; j++)
                KP[tx * 4 + j][ty * 8 + i] = p[j];
        }
        __syncthreads();

        // O += P @ V
#pragma unroll
        for (int c = 0; c < 64; c++) {
            float pr[8], vv[4];
            *(float4*)(pr)     = *(const float4*)&KP[c][ty * 8];
            *(float4*)(pr + 4) = *(const float4*)&KP[c][ty * 8 + 4];
            *(float4*)(vv)     = *(const float4*)&Vs[c][tx * 4];
#pragma unroll
            for (int i = 0; i < 8; i++)
#pragma unroll
                for (int j = 0; j < 4; j++)
                    O[i][j] += pr[i] * vv[j];
        }
        __syncthreads();   // before next tile overwrites KP/Vs
    }

    // epilogue: normalize and write to [B,S,D] with head slice at h*HD
#pragma unroll
    for (int i = 0; i < 8; i++) {
        float inv = 1.0f / l_i[i];
        int srow = q0 + ty * 8 + i;
        float4 o4;
        o4.x = O[i][0] * inv;
        o4.y = O[i][1] * inv;
        o4.z = O[i][2] * inv;
        o4.w = O[i][3] * inv;
        *(float4*)&g_ao[((size_t)(b_ * SS + srow)) * DD + h * HD + tx * 4] = o4;
    }
}

// ---------------------------------------------------------------------------
// Launch
// ---------------------------------------------------------------------------
extern "C" void kernel_launch(void* const* d_in, const int* in_sizes, int n_in,
                              void* d_out, int out_size)
{
    const float* query = (const float*)d_in[0];
    const float* key_  = (const float*)d_in[1];
    const float* value = (const float*)d_in[2];
    const float* Wq = (const float*)d_in[3];
    const float* bq = (const float*)d_in[4];
    const float* Wk = (const float*)d_in[5];
    const float* bk = (const float*)d_in[6];
    const float* Wv = (const float*)d_in[7];
    const float* bv = (const float*)d_in[8];
    const float* Wo = (const float*)d_in[9];
    const float* bo = (const float*)d_in[10];
    float* out = (float*)d_out;

    dim3 ggrid(1024 / 128, MM / 128);   // (8, 32)

    gemm_bias_kernel<<<ggrid, 256>>>(query, Wq, bq, nullptr, 0, 0);
    gemm_bias_kernel<<<ggrid, 256>>>(key_,  Wk, bk, nullptr, 0, 1);
    gemm_bias_kernel<<<ggrid, 256>>>(value, Wv, bv, nullptr, 0, 2);

    flash_attn_kernel<<<dim3(SS / 64, BB * HH), 128>>>();

    gemm_bias_kernel<<<ggrid, 256>>>(nullptr, Wo, bo, out, 1, 3);
}

// round 3
// speedup vs baseline: 5.3081x; 5.3081x over previous
#include <cuda_runtime.h>
#include <cuda_fp16.h>
#include <cstdint>

// Problem constants
#define BB 2
#define SS 2048
#define DD 1024
#define HH 16
#define HD 64
#define MM (BB * SS)   // 4096

// Device-global scratch (allocation-free rule)
__device__ __half g_qh[BB * HH * SS * HD];   // [B,H,S,HD], pre-scaled by 1/8*log2(e)
__device__ __half g_kh[BB * HH * SS * HD];
__device__ __half g_vh[BB * HH * SS * HD];
__device__ float  g_ao[BB * SS * DD];        // attention out, fp32 for precision

// ---------------------------------------------------------------------------
// helpers
// ---------------------------------------------------------------------------
__device__ __forceinline__ uint32_t smem_u32(const void* p) {
    return (uint32_t)__cvta_generic_to_shared(p);
}

__device__ __forceinline__ void ldsm4(uint32_t r[4], uint32_t addr) {
    asm volatile("ldmatrix.sync.aligned.m8n8.x4.shared.b16 {%0,%1,%2,%3}, [%4];\n"
                 : "=r"(r[0]), "=r"(r[1]), "=r"(r[2]), "=r"(r[3]) : "r"(addr));
}
__device__ __forceinline__ void ldsm4t(uint32_t r[4], uint32_t addr) {
    asm volatile("ldmatrix.sync.aligned.m8n8.x4.trans.shared.b16 {%0,%1,%2,%3}, [%4];\n"
                 : "=r"(r[0]), "=r"(r[1]), "=r"(r[2]), "=r"(r[3]) : "r"(addr));
}
__device__ __forceinline__ void mma_16816(float c[4], const uint32_t a[4], const uint32_t b[2]) {
    asm volatile(
        "mma.sync.aligned.m16n8k16.row.col.f32.f16.f16.f32 "
        "{%0,%1,%2,%3}, {%4,%5,%6,%7}, {%8,%9}, {%0,%1,%2,%3};\n"
        : "+f"(c[0]), "+f"(c[1]), "+f"(c[2]), "+f"(c[3])
        : "r"(a[0]), "r"(a[1]), "r"(a[2]), "r"(a[3]), "r"(b[0]), "r"(b[1]));
}
__device__ __forceinline__ uint32_t h2u(__half2 v) {
    return *reinterpret_cast<uint32_t*>(&v);
}

// ---------------------------------------------------------------------------
// GEMM: out = X[M,1024] @ (W*wscale)[1024? no: W[N,K]]^T + bias*wscale
// fp16 tensor-core, BM=128 BN=128 BK=64, 256 threads, 8 warps (4m x 2n).
// src_sel: 0 -> Xp (fp32 param), 1 -> g_ao
// dst_sel: 0/1/2 -> g_qh/g_kh/g_vh (half, scatter [B,H,S,HD]), 3 -> outp fp32
// ---------------------------------------------------------------------------
__global__ __launch_bounds__(256) void gemm_f16_kernel(
    const float* __restrict__ Xp, const float* __restrict__ Wt,
    const float* __restrict__ bias, float* __restrict__ outp,
    float wscale, int src_sel, int dst_sel)
{
    __shared__ __align__(16) __half As[128 * 64];
    __shared__ __align__(16) __half Bs[128 * 64];

    const float* X = src_sel ? g_ao : Xp;
    const int t = threadIdx.x, l = t & 31, w = t >> 5;
    const int g = l >> 3, lr = l & 7;
    const int m0 = blockIdx.y * 128, n0 = blockIdx.x * 128;
    const int wm = (w >> 1) * 32, wn = (w & 1) * 64;

    float acc[2][8][4];
#pragma unroll
    for (int mi = 0; mi < 2; mi++)
#pragma unroll
        for (int nj = 0; nj < 8; nj++)
#pragma unroll
            for (int c = 0; c < 4; c++) acc[mi][nj][c] = 0.0f;

    const uint32_t sA = smem_u32(As), sB = smem_u32(Bs);

    for (int kt = 0; kt < 16; kt++) {
        const int k0 = kt * 64;
#pragma unroll
        for (int i = 0; i < 4; i++) {
            const int id = t + i * 256;
            const int r = id >> 3, c = id & 7;
            const uint32_t soff = (uint32_t)(r * 128 + ((c ^ (r & 7)) * 16));
            {
                const float* p = X + (size_t)(m0 + r) * 1024 + k0 + c * 8;
                float4 f0 = *(const float4*)p;
                float4 f1 = *(const float4*)(p + 4);
                uint4 u;
                u.x = h2u(__floats2half2_rn(f0.x, f0.y));
                u.y = h2u(__floats2half2_rn(f0.z, f0.w));
                u.z = h2u(__floats2half2_rn(f1.x, f1.y));
                u.w = h2u(__floats2half2_rn(f1.z, f1.w));
                *(uint4*)((char*)As + soff) = u;
            }
            {
                const float* p = Wt + (size_t)(n0 + r) * 1024 + k0 + c * 8;
                float4 f0 = *(const float4*)p;
                float4 f1 = *(const float4*)(p + 4);
                uint4 u;
                u.x = h2u(__floats2half2_rn(f0.x * wscale, f0.y * wscale));
                u.y = h2u(__floats2half2_rn(f0.z * wscale, f0.w * wscale));
                u.z = h2u(__floats2half2_rn(f1.x * wscale, f1.y * wscale));
                u.w = h2u(__floats2half2_rn(f1.z * wscale, f1.w * wscale));
                *(uint4*)((char*)Bs + soff) = u;
            }
        }
        __syncthreads();
#pragma unroll
        for (int kk = 0; kk < 4; kk++) {
            uint32_t af[2][4];
#pragma unroll
            for (int mi = 0; mi < 2; mi++) {
                int row = wm + mi * 16 + (g & 1) * 8 + lr;
                int ch = kk * 2 + (g >> 1);
                ldsm4(af[mi], sA + row * 128 + ((ch ^ (row & 7)) * 16));
            }
            uint32_t bf[8][2];
#pragma unroll
            for (int bj = 0; bj < 4; bj++) {
                int row = wn + bj * 16 + (g >> 1) * 8 + lr;
                int ch = kk * 2 + (g & 1);
                uint32_t r4[4];
                ldsm4(r4, sB + row * 128 + ((ch ^ (row & 7)) * 16));
                bf[2 * bj][0] = r4[0];     bf[2 * bj][1] = r4[1];
                bf[2 * bj + 1][0] = r4[2]; bf[2 * bj + 1][1] = r4[3];
            }
#pragma unroll
            for (int mi = 0; mi < 2; mi++)
#pragma unroll
                for (int nj = 0; nj < 8; nj++)
                    mma_16816(acc[mi][nj], af[mi], bf[nj]);
        }
        __syncthreads();
    }

    // epilogue
    if (dst_sel == 3) {
#pragma unroll
        for (int mi = 0; mi < 2; mi++)
#pragma unroll
            for (int nj = 0; nj < 8; nj++) {
                int m = m0 + wm + mi * 16 + (l >> 2);
                int n = n0 + wn + nj * 8 + (l & 3) * 2;
                float2 b2 = *(const float2*)&bias[n];
                float2 v0 = { acc[mi][nj][0] + b2.x, acc[mi][nj][1] + b2.y };
                float2 v1 = { acc[mi][nj][2] + b2.x, acc[mi][nj][3] + b2.y };
                *(float2*)&outp[(size_t)m * 1024 + n] = v0;
                *(float2*)&outp[(size_t)(m + 8) * 1024 + n] = v1;
            }
    } else {
        __half* dst = (dst_sel == 0) ? g_qh : (dst_sel == 1) ? g_kh : g_vh;
#pragma unroll
        for (int mi = 0; mi < 2; mi++)
#pragma unroll
            for (int nj = 0; nj < 8; nj++) {
                int m = m0 + wm + mi * 16 + (l >> 2);
                int n = n0 + wn + nj * 8 + (l & 3) * 2;
                float2 b2 = *(const float2*)&bias[n];
                int h = n >> 6, e = n & 63;
                int b_ = m >> 11;
                int s0 = m & 2047, s1 = (m + 8) & 2047;
                __half2 h0 = __floats2half2_rn(acc[mi][nj][0] + b2.x * wscale,
                                               acc[mi][nj][1] + b2.y * wscale);
                __half2 h1 = __floats2half2_rn(acc[mi][nj][2] + b2.x * wscale,
                                               acc[mi][nj][3] + b2.y * wscale);
                *(__half2*)&dst[(((size_t)(b_ * HH + h)) * SS + s0) * HD + e] = h0;
                *(__half2*)&dst[(((size_t)(b_ * HH + h)) * SS + s1) * HD + e] = h1;
            }
    }
}

// ---------------------------------------------------------------------------
// Flash attention, fp16 tensor-core. BQ=128, BKV=64, 256 threads (8 warps,
// each owns 16 q rows). Q fragments register-resident; P stays in registers.
// Scores are in log2 domain (Q pre-scaled by 1/8*log2(e) at projection).
// ---------------------------------------------------------------------------
__global__ __launch_bounds__(256) void flash_f16_kernel()
{
    __shared__ __align__(16) __half Qs[128 * 64];
    __shared__ __align__(16) __half Ks[64 * 64];
    __shared__ __align__(16) __half Vs[64 * 64];

    const int t = threadIdx.x, l = t & 31, w = t >> 5;
    const int g = l >> 3, lr = l & 7;
    const int bh = blockIdx.y, qt = blockIdx.x;
    const int b_ = bh >> 4, h = bh & 15;
    const __half* qb = g_qh + (size_t)bh * SS * HD + (size_t)qt * 128 * HD;
    const __half* kb = g_kh + (size_t)bh * SS * HD;
    const __half* vb = g_vh + (size_t)bh * SS * HD;

    const uint32_t sQ = smem_u32(Qs), sK = smem_u32(Ks), sV = smem_u32(Vs);

    // stage Q (128x64 half) into smem, then extract register fragments
#pragma unroll
    for (int i = 0; i < 4; i++) {
        const int id = t + i * 256;
        const int r = id >> 3, c = id & 7;
        *(uint4*)((char*)Qs + r * 128 + ((c ^ (r & 7)) * 16)) =
            *(const uint4*)(qb + (size_t)r * HD + c * 8);
    }
    __syncthreads();

    uint32_t qf[4][4];
#pragma unroll
    for (int kk = 0; kk < 4; kk++) {
        int row = w * 16 + (g & 1) * 8 + lr;
        int ch = kk * 2 + (g >> 1);
        ldsm4(qf[kk], sQ + row * 128 + ((ch ^ (row & 7)) * 16));
    }

    float mrow[2] = { -1e30f, -1e30f };
    float lrow[2] = { 0.0f, 0.0f };
    float O[8][4];
#pragma unroll
    for (int nj = 0; nj < 8; nj++)
#pragma unroll
        for (int c = 0; c < 4; c++) O[nj][c] = 0.0f;

    for (int kv = 0; kv < SS; kv += 64) {
        __syncthreads();  // prior-iteration consumers done with Ks/Vs
#pragma unroll
        for (int i = 0; i < 2; i++) {
            const int id = t + i * 256;
            const int r = id >> 3, c = id & 7;
            const uint32_t soff = (uint32_t)(r * 128 + ((c ^ (r & 7)) * 16));
            *(uint4*)((char*)Ks + soff) = *(const uint4*)(kb + (size_t)(kv + r) * HD + c * 8);
            *(uint4*)((char*)Vs + soff) = *(const uint4*)(vb + (size_t)(kv + r) * HD + c * 8);
        }
        __syncthreads();

        // S = Q K^T  (log2 domain)
        float S[8][4];
#pragma unroll
        for (int nj = 0; nj < 8; nj++)
#pragma unroll
            for (int c = 0; c < 4; c++) S[nj][c] = 0.0f;
#pragma unroll
        for (int kk = 0; kk < 4; kk++) {
            uint32_t bf[8][2];
#pragma unroll
            for (int bj = 0; bj < 4; bj++) {
                int row = bj * 16 + (g >> 1) * 8 + lr;
                int ch = kk * 2 + (g & 1);
                uint32_t r4[4];
                ldsm4(r4, sK + row * 128 + ((ch ^ (row & 7)) * 16));
                bf[2 * bj][0] = r4[0];     bf[2 * bj][1] = r4[1];
                bf[2 * bj + 1][0] = r4[2]; bf[2 * bj + 1][1] = r4[3];
            }
#pragma unroll
            for (int nj = 0; nj < 8; nj++)
                mma_16816(S[nj], qf[kk], bf[nj]);
        }

        // online softmax (rows: l>>2 and l>>2 + 8)
        float mt0 = -1e30f, mt1 = -1e30f;
#pragma unroll
        for (int nj = 0; nj < 8; nj++) {
            mt0 = fmaxf(mt0, fmaxf(S[nj][0], S[nj][1]));
            mt1 = fmaxf(mt1, fmaxf(S[nj][2], S[nj][3]));
        }
        mt0 = fmaxf(mt0, __shfl_xor_sync(0xffffffffu, mt0, 1));
        mt0 = fmaxf(mt0, __shfl_xor_sync(0xffffffffu, mt0, 2));
        mt1 = fmaxf(mt1, __shfl_xor_sync(0xffffffffu, mt1, 1));
        mt1 = fmaxf(mt1, __shfl_xor_sync(0xffffffffu, mt1, 2));
        float mn0 = fmaxf(mrow[0], mt0);
        float mn1 = fmaxf(mrow[1], mt1);
        float a0 = exp2f(mrow[0] - mn0);
        float a1 = exp2f(mrow[1] - mn1);
        mrow[0] = mn0; mrow[1] = mn1;

        float rs0 = 0.0f, rs1 = 0.0f;
        uint32_t pf[4][4];
#pragma unroll
        for (int nj = 0; nj < 8; nj++) {
            float p0 = exp2f(S[nj][0] - mn0);
            float p1 = exp2f(S[nj][1] - mn0);
            float p2 = exp2f(S[nj][2] - mn1);
            float p3 = exp2f(S[nj][3] - mn1);
            rs0 += p0 + p1;
            rs1 += p2 + p3;
            int j = nj >> 1, hi = nj & 1;
            pf[j][hi * 2 + 0] = h2u(__floats2half2_rn(p0, p1));
            pf[j][hi * 2 + 1] = h2u(__floats2half2_rn(p2, p3));
        }
        rs0 += __shfl_xor_sync(0xffffffffu, rs0, 1);
        rs0 += __shfl_xor_sync(0xffffffffu, rs0, 2);
        rs1 += __shfl_xor_sync(0xffffffffu, rs1, 1);
        rs1 += __shfl_xor_sync(0xffffffffu, rs1, 2);
        lrow[0] = lrow[0] * a0 + rs0;
        lrow[1] = lrow[1] * a1 + rs1;

#pragma unroll
        for (int nj = 0; nj < 8; nj++) {
            O[nj][0] *= a0; O[nj][1] *= a0;
            O[nj][2] *= a1; O[nj][3] *= a1;
        }

        // O += P @ V  (V via ldmatrix.trans: B[k=kv][n=hd] from row-major V)
#pragma unroll
        for (int kk = 0; kk < 4; kk++) {
            uint32_t bf[8][2];
#pragma unroll
            for (int bj = 0; bj < 4; bj++) {
                int row = kk * 16 + (g & 1) * 8 + lr;
                int ch = bj * 2 + (g >> 1);
                uint32_t r4[4];
                ldsm4t(r4, sV + row * 128 + ((ch ^ (row & 7)) * 16));
                bf[2 * bj][0] = r4[0];     bf[2 * bj][1] = r4[1];
                bf[2 * bj + 1][0] = r4[2]; bf[2 * bj + 1][1] = r4[3];
            }
#pragma unroll
            for (int nj = 0; nj < 8; nj++)
                mma_16816(O[nj], pf[kk], bf[nj]);
        }
    }

    // epilogue: normalize, write fp32 to g_ao[B,S,D] head slice
    float inv0 = 1.0f / lrow[0];
    float inv1 = 1.0f / lrow[1];
    int srow = qt * 128 + w * 16 + (l >> 2);
    float* ob = g_ao + ((size_t)b_ * SS + srow) * DD + h * 64;
#pragma unroll
    for (int nj = 0; nj < 8; nj++) {
        int n = nj * 8 + (l & 3) * 2;
        float2 v0 = { O[nj][0] * inv0, O[nj][1] * inv0 };
        float2 v1 = { O[nj][2] * inv1, O[nj][3] * inv1 };
        *(float2*)&ob[n] = v0;
        *(float2*)(ob + 8 * DD + n) = v1;
    }
}

// ---------------------------------------------------------------------------
// Launch
// ---------------------------------------------------------------------------
extern "C" void kernel_launch(void* const* d_in, const int* in_sizes, int n_in,
                              void* d_out, int out_size)
{
    const float* query = (const float*)d_in[0];
    const float* key_  = (const float*)d_in[1];
    const float* value = (const float*)d_in[2];
    const float* Wq = (const float*)d_in[3];
    const float* bq = (const float*)d_in[4];
    const float* Wk = (const float*)d_in[5];
    const float* bk = (const float*)d_in[6];
    const float* Wv = (const float*)d_in[7];
    const float* bv = (const float*)d_in[8];
    const float* Wo = (const float*)d_in[9];
    const float* bo = (const float*)d_in[10];
    float* out = (float*)d_out;

    dim3 ggrid(1024 / 128, MM / 128);   // (8, 32)
    const float QSC = 0.125f * 1.44269504088896340736f; // 1/sqrt(64) * log2(e)

    gemm_f16_kernel<<<ggrid, 256>>>(query, Wq, bq, nullptr, QSC,  0, 0);
    gemm_f16_kernel<<<ggrid, 256>>>(key_,  Wk, bk, nullptr, 1.0f, 0, 1);
    gemm_f16_kernel<<<ggrid, 256>>>(value, Wv, bv, nullptr, 1.0f, 0, 2);

    flash_f16_kernel<<<dim3(SS / 128, BB * HH), 256>>>();

    gemm_f16_kernel<<<ggrid, 256>>>(nullptr, Wo, bo, out, 1.0f, 1, 3);
}

// round 4
// speedup vs baseline: 8.8648x; 1.6701x over previous
#include <cuda_runtime.h>
#include <cuda_fp16.h>
#include <cstdint>

// Problem constants
#define BB 2
#define SS 2048
#define DD 1024
#define HH 16
#define HD 64
#define MM (BB * SS)   // 4096

// Device-global scratch (allocation-free rule)
__device__ __half g_xq[MM * DD], g_xk[MM * DD], g_xv[MM * DD];      // fp16 inputs
__device__ __half g_wq[DD * DD], g_wk[DD * DD], g_wv[DD * DD], g_wo[DD * DD];
__device__ __half g_qh[MM * DD], g_kh[MM * DD], g_vh[MM * DD];      // [B,H,S,HD]
__device__ __half g_aoh[MM * DD];                                   // attn out fp16

// ---------------------------------------------------------------------------
// helpers
// ---------------------------------------------------------------------------
__device__ __forceinline__ uint32_t smem_u32(const void* p) {
    return (uint32_t)__cvta_generic_to_shared(p);
}
__device__ __forceinline__ void ldsm4(uint32_t r[4], uint32_t addr) {
    asm volatile("ldmatrix.sync.aligned.m8n8.x4.shared.b16 {%0,%1,%2,%3}, [%4];\n"
                 : "=r"(r[0]), "=r"(r[1]), "=r"(r[2]), "=r"(r[3]) : "r"(addr));
}
__device__ __forceinline__ void ldsm4t(uint32_t r[4], uint32_t addr) {
    asm volatile("ldmatrix.sync.aligned.m8n8.x4.trans.shared.b16 {%0,%1,%2,%3}, [%4];\n"
                 : "=r"(r[0]), "=r"(r[1]), "=r"(r[2]), "=r"(r[3]) : "r"(addr));
}
__device__ __forceinline__ void mma_16816(float c[4], const uint32_t a[4], const uint32_t b[2]) {
    asm volatile(
        "mma.sync.aligned.m16n8k16.row.col.f32.f16.f16.f32 "
        "{%0,%1,%2,%3}, {%4,%5,%6,%7}, {%8,%9}, {%0,%1,%2,%3};\n"
        : "+f"(c[0]), "+f"(c[1]), "+f"(c[2]), "+f"(c[3])
        : "r"(a[0]), "r"(a[1]), "r"(a[2]), "r"(a[3]), "r"(b[0]), "r"(b[1]));
}
__device__ __forceinline__ uint32_t h2u(__half2 v) {
    return *reinterpret_cast<uint32_t*>(&v);
}
__device__ __forceinline__ void cp_async16(uint32_t saddr, const void* g) {
    asm volatile("cp.async.cg.shared.global [%0], [%1], 16;\n" :: "r"(saddr), "l"(g));
}
__device__ __forceinline__ void cp_commit() {
    asm volatile("cp.async.commit_group;\n");
}
template <int N>
__device__ __forceinline__ void cp_wait() {
    asm volatile("cp.async.wait_group %0;\n" :: "n"(N));
}

// ---------------------------------------------------------------------------
// Convert fp32 -> fp16 for inputs and weights (Wq pre-scaled by 1/8*log2 e)
// 4194304 float4 total: [q 1M][k 1M][v 1M][wq 256K][wk 256K][wv 256K][wo 256K]
// ---------------------------------------------------------------------------
__global__ __launch_bounds__(1024) void convert_kernel(
    const float* __restrict__ q, const float* __restrict__ k, const float* __restrict__ v,
    const float* __restrict__ wq, const float* __restrict__ wk,
    const float* __restrict__ wv, const float* __restrict__ wo, float qsc)
{
    const int XN = MM * DD / 4;   // 1048576
    const int WN = DD * DD / 4;   // 262144
    int idx = blockIdx.x * blockDim.x + threadIdx.x;
    const float* src;
    __half* dst;
    float sc = 1.0f;
    if (idx < XN)            { src = q; dst = g_xq; }
    else if (idx < 2 * XN)   { src = k; dst = g_xk; idx -= XN; }
    else if (idx < 3 * XN)   { src = v; dst = g_xv; idx -= 2 * XN; }
    else {
        int j = idx - 3 * XN;
        if (j < WN)          { src = wq; dst = g_wq; sc = qsc; }
        else if (j < 2 * WN) { src = wk; dst = g_wk; j -= WN; }
        else if (j < 3 * WN) { src = wv; dst = g_wv; j -= 2 * WN; }
        else                 { src = wo; dst = g_wo; j -= 3 * WN; }
        idx = j;
    }
    float4 f = ((const float4*)src)[idx];
    uint2 u;
    u.x = h2u(__floats2half2_rn(f.x * sc, f.y * sc));
    u.y = h2u(__floats2half2_rn(f.z * sc, f.w * sc));
    ((uint2*)dst)[idx] = u;
}

// ---------------------------------------------------------------------------
// Pipelined fp16 GEMM pieces (BM=128, BN=128, BK=64, 3-stage cp.async)
// ---------------------------------------------------------------------------
__device__ __forceinline__ void stage_load(
    uint32_t sA, uint32_t sB, const __half* __restrict__ X,
    const __half* __restrict__ W, int m0, int n0, int k0, int t)
{
#pragma unroll
    for (int i = 0; i < 4; i++) {
        int id = t + i * 256;
        int r = id >> 3, c = id & 7;
        uint32_t so = (uint32_t)(r * 128 + ((c ^ (r & 7)) * 16));
        cp_async16(sA + so, X + (size_t)(m0 + r) * DD + k0 + c * 8);
        cp_async16(sB + so, W + (size_t)(n0 + r) * DD + k0 + c * 8);
    }
}

__device__ __forceinline__ void mma_tile(
    uint32_t sA, uint32_t sB, float (&acc)[2][8][4],
    int wm, int wn, int g, int lr)
{
#pragma unroll
    for (int kk = 0; kk < 4; kk++) {
        uint32_t af[2][4];
#pragma unroll
        for (int mi = 0; mi < 2; mi++) {
            int row = wm + mi * 16 + (g & 1) * 8 + lr;
            int ch = kk * 2 + (g >> 1);
            ldsm4(af[mi], sA + row * 128 + ((ch ^ (row & 7)) * 16));
        }
        uint32_t bf[8][2];
#pragma unroll
        for (int bj = 0; bj < 4; bj++) {
            int row = wn + bj * 16 + (g >> 1) * 8 + lr;
            int ch = kk * 2 + (g & 1);
            uint32_t r4[4];
            ldsm4(r4, sB + row * 128 + ((ch ^ (row & 7)) * 16));
            bf[2 * bj][0] = r4[0];     bf[2 * bj][1] = r4[1];
            bf[2 * bj + 1][0] = r4[2]; bf[2 * bj + 1][1] = r4[3];
        }
#pragma unroll
        for (int mi = 0; mi < 2; mi++)
#pragma unroll
            for (int nj = 0; nj < 8; nj++)
                mma_16816(acc[mi][nj], af[mi], bf[nj]);
    }
}

// OPROJ=0: z in {0,1,2} selects q/k/v projection, writes half scatter [B,H,S,HD]
// OPROJ=1: out = g_aoh @ g_wo^T + bo, fp32 row-major
template <int OPROJ>
__global__ __launch_bounds__(256, 2) void gemm_pipe_kernel(
    const float* __restrict__ b0, const float* __restrict__ b1,
    const float* __restrict__ b2v, float* __restrict__ outp, float qsc)
{
    extern __shared__ __align__(16) __half smp[];
    const int t = threadIdx.x, l = t & 31, w = t >> 5;
    const int g = l >> 3, lr = l & 7;
    const int m0 = blockIdx.y * 128, n0 = blockIdx.x * 128;
    const int wm = (w >> 1) * 32, wn = (w & 1) * 64;

    const __half *X, *W;
    const float* bias;
    float bsc = 1.0f;
    int z = 0;
    if (OPROJ) {
        X = g_aoh; W = g_wo; bias = b0;
    } else {
        z = blockIdx.z;
        X = (z == 0) ? g_xq : (z == 1) ? g_xk : g_xv;
        W = (z == 0) ? g_wq : (z == 1) ? g_wk : g_wv;
        bias = (z == 0) ? b0 : (z == 1) ? b1 : b2v;
        if (z == 0) bsc = qsc;
    }

    const uint32_t sb = smem_u32(smp);
    float acc[2][8][4];
#pragma unroll
    for (int mi = 0; mi < 2; mi++)
#pragma unroll
        for (int nj = 0; nj < 8; nj++)
#pragma unroll
            for (int c = 0; c < 4; c++) acc[mi][nj][c] = 0.0f;

    // prologue: stages 0,1
    stage_load(sb,          sb + 16384,          X, W, m0, n0, 0,  t); cp_commit();
    stage_load(sb + 32768,  sb + 32768 + 16384,  X, W, m0, n0, 64, t); cp_commit();

    for (int kt = 0; kt < 16; kt++) {
        if (kt + 2 < 16) {
            int s2 = (kt + 2) % 3;
            stage_load(sb + s2 * 32768, sb + s2 * 32768 + 16384,
                       X, W, m0, n0, (kt + 2) * 64, t);
            cp_commit();
            cp_wait<2>();
        } else if (kt + 1 < 16) {
            cp_wait<1>();
        } else {
            cp_wait<0>();
        }
        __syncthreads();
        int s = kt % 3;
        mma_tile(sb + s * 32768, sb + s * 32768 + 16384, acc, wm, wn, g, lr);
        __syncthreads();
    }

    if (OPROJ) {
#pragma unroll
        for (int mi = 0; mi < 2; mi++)
#pragma unroll
            for (int nj = 0; nj < 8; nj++) {
                int m = m0 + wm + mi * 16 + (l >> 2);
                int n = n0 + wn + nj * 8 + (l & 3) * 2;
                float2 b2 = *(const float2*)&bias[n];
                float2 v0 = { acc[mi][nj][0] + b2.x, acc[mi][nj][1] + b2.y };
                float2 v1 = { acc[mi][nj][2] + b2.x, acc[mi][nj][3] + b2.y };
                *(float2*)&outp[(size_t)m * DD + n] = v0;
                *(float2*)&outp[(size_t)(m + 8) * DD + n] = v1;
            }
    } else {
        __half* dst = (z == 0) ? g_qh : (z == 1) ? g_kh : g_vh;
#pragma unroll
        for (int mi = 0; mi < 2; mi++)
#pragma unroll
            for (int nj = 0; nj < 8; nj++) {
                int m = m0 + wm + mi * 16 + (l >> 2);
                int n = n0 + wn + nj * 8 + (l & 3) * 2;
                float2 b2 = *(const float2*)&bias[n];
                int h = n >> 6, e = n & 63;
                int b_ = m >> 11;
                int s0 = m & 2047, s1 = (m + 8) & 2047;
                __half2 h0 = __floats2half2_rn(acc[mi][nj][0] + b2.x * bsc,
                                               acc[mi][nj][1] + b2.y * bsc);
                __half2 h1 = __floats2half2_rn(acc[mi][nj][2] + b2.x * bsc,
                                               acc[mi][nj][3] + b2.y * bsc);
                *(__half2*)&dst[(((size_t)(b_ * HH + h)) * SS + s0) * HD + e] = h0;
                *(__half2*)&dst[(((size_t)(b_ * HH + h)) * SS + s1) * HD + e] = h1;
            }
    }
}

// ---------------------------------------------------------------------------
// Flash attention, fp16 tensor-core, cp.async double-buffered K/V.
// BQ=128, BKV=64, 256 threads (8 warps of 16 q-rows each).
// ---------------------------------------------------------------------------
__global__ __launch_bounds__(256, 2) void flash_f16_kernel()
{
    __shared__ __align__(16) __half Qs[128 * 64];
    __shared__ __align__(16) __half Ks[2][64 * 64];
    __shared__ __align__(16) __half Vs[2][64 * 64];

    const int t = threadIdx.x, l = t & 31, w = t >> 5;
    const int g = l >> 3, lr = l & 7;
    const int bh = blockIdx.y, qt = blockIdx.x;
    const int b_ = bh >> 4, h = bh & 15;
    const __half* qb = g_qh + (size_t)bh * SS * HD + (size_t)qt * 128 * HD;
    const __half* kb = g_kh + (size_t)bh * SS * HD;
    const __half* vb = g_vh + (size_t)bh * SS * HD;

    const uint32_t sQ = smem_u32(Qs);
    const uint32_t sK = smem_u32(Ks);
    const uint32_t sV = smem_u32(Vs);

    // Q tile via cp.async (group 0)
#pragma unroll
    for (int i = 0; i < 4; i++) {
        const int id = t + i * 256;
        const int r = id >> 3, c = id & 7;
        uint32_t so = (uint32_t)(r * 128 + ((c ^ (r & 7)) * 16));
        cp_async16(sQ + so, qb + (size_t)r * HD + c * 8);
    }
    cp_commit();

    auto issue_kv = [&](int tile, int bi) {
#pragma unroll
        for (int i = 0; i < 2; i++) {
            const int id = t + i * 256;
            const int r = id >> 3, c = id & 7;
            uint32_t so = (uint32_t)(bi * 8192 + r * 128 + ((c ^ (r & 7)) * 16));
            cp_async16(sK + so, kb + (size_t)(tile * 64 + r) * HD + c * 8);
            cp_async16(sV + so, vb + (size_t)(tile * 64 + r) * HD + c * 8);
        }
    };

    issue_kv(0, 0);
    cp_commit();
    cp_wait<1>();          // Q done, kv0 may be in flight
    __syncthreads();

    uint32_t qf[4][4];
#pragma unroll
    for (int kk = 0; kk < 4; kk++) {
        int row = w * 16 + (g & 1) * 8 + lr;
        int ch = kk * 2 + (g >> 1);
        ldsm4(qf[kk], sQ + row * 128 + ((ch ^ (row & 7)) * 16));
    }

    float mrow[2] = { -1e30f, -1e30f };
    float lrow[2] = { 0.0f, 0.0f };
    float O[8][4];
#pragma unroll
    for (int nj = 0; nj < 8; nj++)
#pragma unroll
        for (int c = 0; c < 4; c++) O[nj][c] = 0.0f;

    for (int tile = 0; tile < 32; tile++) {
        if (tile + 1 < 32) {
            issue_kv(tile + 1, (tile + 1) & 1);
            cp_commit();
            cp_wait<1>();
        } else {
            cp_wait<0>();
        }
        __syncthreads();
        const uint32_t sKb = sK + (tile & 1) * 8192;
        const uint32_t sVb = sV + (tile & 1) * 8192;

        // S = Q K^T  (log2 domain; Q pre-scaled)
        float S[8][4];
#pragma unroll
        for (int nj = 0; nj < 8; nj++)
#pragma unroll
            for (int c = 0; c < 4; c++) S[nj][c] = 0.0f;
#pragma unroll
        for (int kk = 0; kk < 4; kk++) {
            uint32_t bf[8][2];
#pragma unroll
            for (int bj = 0; bj < 4; bj++) {
                int row = bj * 16 + (g >> 1) * 8 + lr;
                int ch = kk * 2 + (g & 1);
                uint32_t r4[4];
                ldsm4(r4, sKb + row * 128 + ((ch ^ (row & 7)) * 16));
                bf[2 * bj][0] = r4[0];     bf[2 * bj][1] = r4[1];
                bf[2 * bj + 1][0] = r4[2]; bf[2 * bj + 1][1] = r4[3];
            }
#pragma unroll
            for (int nj = 0; nj < 8; nj++)
                mma_16816(S[nj], qf[kk], bf[nj]);
        }

        // online softmax (rows l>>2 and l>>2 + 8)
        float mt0 = -1e30f, mt1 = -1e30f;
#pragma unroll
        for (int nj = 0; nj < 8; nj++) {
            mt0 = fmaxf(mt0, fmaxf(S[nj][0], S[nj][1]));
            mt1 = fmaxf(mt1, fmaxf(S[nj][2], S[nj][3]));
        }
        mt0 = fmaxf(mt0, __shfl_xor_sync(0xffffffffu, mt0, 1));
        mt0 = fmaxf(mt0, __shfl_xor_sync(0xffffffffu, mt0, 2));
        mt1 = fmaxf(mt1, __shfl_xor_sync(0xffffffffu, mt1, 1));
        mt1 = fmaxf(mt1, __shfl_xor_sync(0xffffffffu, mt1, 2));
        float mn0 = fmaxf(mrow[0], mt0);
        float mn1 = fmaxf(mrow[1], mt1);
        float a0 = exp2f(mrow[0] - mn0);
        float a1 = exp2f(mrow[1] - mn1);
        mrow[0] = mn0; mrow[1] = mn1;

        float rs0 = 0.0f, rs1 = 0.0f;
        uint32_t pf[4][4];
#pragma unroll
        for (int nj = 0; nj < 8; nj++) {
            float p0 = exp2f(S[nj][0] - mn0);
            float p1 = exp2f(S[nj][1] - mn0);
            float p2 = exp2f(S[nj][2] - mn1);
            float p3 = exp2f(S[nj][3] - mn1);
            rs0 += p0 + p1;
            rs1 += p2 + p3;
            int j = nj >> 1, hi = nj & 1;
            pf[j][hi * 2 + 0] = h2u(__floats2half2_rn(p0, p1));
            pf[j][hi * 2 + 1] = h2u(__floats2half2_rn(p2, p3));
        }
        rs0 += __shfl_xor_sync(0xffffffffu, rs0, 1);
        rs0 += __shfl_xor_sync(0xffffffffu, rs0, 2);
        rs1 += __shfl_xor_sync(0xffffffffu, rs1, 1);
        rs1 += __shfl_xor_sync(0xffffffffu, rs1, 2);
        lrow[0] = lrow[0] * a0 + rs0;
        lrow[1] = lrow[1] * a1 + rs1;

#pragma unroll
        for (int nj = 0; nj < 8; nj++) {
            O[nj][0] *= a0; O[nj][1] *= a0;
            O[nj][2] *= a1; O[nj][3] *= a1;
        }

        // O += P @ V
#pragma unroll
        for (int kk = 0; kk < 4; kk++) {
            uint32_t bf[8][2];
#pragma unroll
            for (int bj = 0; bj < 4; bj++) {
                int row = kk * 16 + (g & 1) * 8 + lr;
                int ch = bj * 2 + (g >> 1);
                uint32_t r4[4];
                ldsm4t(r4, sVb + row * 128 + ((ch ^ (row & 7)) * 16));
                bf[2 * bj][0] = r4[0];     bf[2 * bj][1] = r4[1];
                bf[2 * bj + 1][0] = r4[2]; bf[2 * bj + 1][1] = r4[3];
            }
#pragma unroll
            for (int nj = 0; nj < 8; nj++)
                mma_16816(O[nj], pf[kk], bf[nj]);
        }
        __syncthreads();   // before buffer reuse next iteration
    }

    // epilogue: normalize, write fp16 to g_aoh[B,S,D] head slice
    float inv0 = 1.0f / lrow[0];
    float inv1 = 1.0f / lrow[1];
    int srow = qt * 128 + w * 16 + (l >> 2);
    __half* ob = g_aoh + ((size_t)b_ * SS + srow) * DD + h * 64;
#pragma unroll
    for (int nj = 0; nj < 8; nj++) {
        int n = nj * 8 + (l & 3) * 2;
        __half2 v0 = __floats2half2_rn(O[nj][0] * inv0, O[nj][1] * inv0);
        __half2 v1 = __floats2half2_rn(O[nj][2] * inv1, O[nj][3] * inv1);
        *(__half2*)&ob[n] = v0;
        *(__half2*)(ob + 8 * DD + n) = v1;
    }
}

// ---------------------------------------------------------------------------
// Launch
// ---------------------------------------------------------------------------
extern "C" void kernel_launch(void* const* d_in, const int* in_sizes, int n_in,
                              void* d_out, int out_size)
{
    const float* query = (const float*)d_in[0];
    const float* key_  = (const float*)d_in[1];
    const float* value = (const float*)d_in[2];
    const float* Wq = (const float*)d_in[3];
    const float* bq = (const float*)d_in[4];
    const float* Wk = (const float*)d_in[5];
    const float* bk = (const float*)d_in[6];
    const float* Wv = (const float*)d_in[7];
    const float* bv = (const float*)d_in[8];
    const float* Wo = (const float*)d_in[9];
    const float* bo = (const float*)d_in[10];
    float* out = (float*)d_out;

    const float QSC = 0.125f * 1.44269504088896340736f; // 1/sqrt(64) * log2(e)
    const int GSMEM = 3 * 32768;   // 96KB dynamic

    cudaFuncSetAttribute(gemm_pipe_kernel<0>,
                         cudaFuncAttributeMaxDynamicSharedMemorySize, GSMEM);
    cudaFuncSetAttribute(gemm_pipe_kernel<1>,
                         cudaFuncAttributeMaxDynamicSharedMemorySize, GSMEM);

    convert_kernel<<<4096, 1024>>>(query, key_, value, Wq, Wk, Wv, Wo, QSC);

    gemm_pipe_kernel<0><<<dim3(8, 32, 3), 256, GSMEM>>>(bq, bk, bv, nullptr, QSC);

    flash_f16_kernel<<<dim3(SS / 128, BB * HH), 256>>>();

    gemm_pipe_kernel<1><<<dim3(8, 32), 256, GSMEM>>>(bo, nullptr, nullptr, out, 1.0f);
}